// round 7
// baseline (speedup 1.0000x reference)
#include <cuda_runtime.h>
#include <cuda_bf16.h>
#include <stdint.h>
#include <math.h>

// ---------------------------------------------------------------------------
// Mamba block forward.  B=2, L=2048, d_model=1024, d_inner=2048,
// d_state=16, dt_rank=64, d_conv=4
// ---------------------------------------------------------------------------
#define LSEQ   2048
#define BATCH  2
#define DM     1024
#define DI     2048
#define NST    16
#define DTR    64
#define MROWS  (BATCH * LSEQ)   // 4096
#define NPROJ  96               // dt_rank + 2*d_state

// ------------------------- scratch (static device mem) ---------------------
__device__ float g_xr[(size_t)MROWS * (2 * DI)];   // in-proj output (xin|res)
__device__ float g_u[(size_t)MROWS * DI];          // silu(conv(xin))
__device__ float g_xdbl[(size_t)MROWS * NPROJ];    // u @ W_x
__device__ float g_delta[(size_t)MROWS * DI];      // softplus(dlt@W_dt + b)

// bf16x3 expanded operands: A' = [ah|al|ah] (M x 3K),  B'^T = [bh|bh|bl] (N x 3K)
__device__ __align__(1024) __nv_bfloat16 g_xbf  [(size_t)MROWS * (3 * DM)];
__device__ __align__(1024) __nv_bfloat16 g_wibf [(size_t)(2 * DI) * (3 * DM)];
__device__ __align__(1024) __nv_bfloat16 g_ybf  [(size_t)MROWS * (3 * DI)];   // written by scan
__device__ __align__(1024) __nv_bfloat16 g_wobf [(size_t)DM * (3 * DI)];
__device__ __align__(1024) __nv_bfloat16 g_xdblbf[(size_t)MROWS * (3 * DTR)];
__device__ __align__(1024) __nv_bfloat16 g_wdtbf [(size_t)DI * (3 * DTR)];

// ------------------------- helpers ------------------------------------------
__device__ __forceinline__ float fast_ex2(float x) {
    float y;
    asm("ex2.approx.f32 %0, %1;" : "=f"(y) : "f"(x));
    return y;
}
__device__ __forceinline__ uint32_t smem_u32(const void* p) {
    uint32_t a;
    asm("{ .reg .u64 t; cvta.to.shared.u64 t, %1; cvt.u32.u64 %0, t; }" : "=r"(a) : "l"(p));
    return a;
}
__device__ __forceinline__ void cp_async16(uint32_t saddr, const void* gptr) {
    asm volatile("cp.async.cg.shared.global [%0], [%1], 16;\n" :: "r"(saddr), "l"(gptr));
}
__device__ __forceinline__ void cp_commit() {
    asm volatile("cp.async.commit_group;\n");
}
template <int NWAIT> __device__ __forceinline__ void cp_wait() {
    asm volatile("cp.async.wait_group %0;\n" :: "n"(NWAIT));
}

#define LDSM_X4(r, addr)                                                       \
    asm volatile("ldmatrix.sync.aligned.m8n8.x4.shared.b16 {%0,%1,%2,%3}, [%4];" \
                 : "=r"((r)[0]), "=r"((r)[1]), "=r"((r)[2]), "=r"((r)[3])      \
                 : "r"(addr))

#define MMA_BF16(ACC, Aq, B0, B1)                                              \
    asm volatile(                                                              \
        "mma.sync.aligned.m16n8k16.row.col.f32.bf16.bf16.f32 "                 \
        "{%0,%1,%2,%3}, {%4,%5,%6,%7}, {%8,%9}, {%0,%1,%2,%3};\n"              \
        : "+f"(ACC[0]), "+f"(ACC[1]), "+f"(ACC[2]), "+f"(ACC[3])               \
        : "r"((Aq)[0]), "r"((Aq)[1]), "r"((Aq)[2]), "r"((Aq)[3]),              \
          "r"(B0), "r"(B1))

// ============================================================================
// bf16 tensor-core GEMM:  C(MxN fp32) = A(M x K) @ B(N x K)^T,  bf16 inputs.
// CTA 256x128, BK=64, 8 warps (4x2), warp tile 64x64, m16n8k16.
// 3-stage cp.async pipeline, XOR-swizzled smem, ldmatrix fragment loads.
// epi: 0 = plain store, 1 = softplus(acc + bias[col]).
// ============================================================================
#define BM 256
#define BN 128
#define BKB 64
#define A_TILE_BYTES (BM * BKB * 2)      // 32768
#define B_TILE_BYTES (BN * BKB * 2)      // 16384
#define STG_BYTES (A_TILE_BYTES + B_TILE_BYTES)   // 49152
#define NSTAGE 3
#define GEMM_SMEM (NSTAGE * STG_BYTES)   // 147456

__device__ __forceinline__ void load_tile_bf(
    const __nv_bfloat16* __restrict__ A, const __nv_bfloat16* __restrict__ B,
    int K, int brow, int bcol, int k0, char* sA, char* sB, int tid)
{
#pragma unroll
    for (int i = 0; i < 8; i++) {             // A: 256 rows x 8 chunks of 16B
        int ch = tid + i * 256;
        int r = ch >> 3, c = ch & 7;
        const __nv_bfloat16* g = A + (size_t)(brow + r) * K + k0 + c * 8;
        cp_async16(smem_u32(sA + r * 128 + ((c ^ (r & 7)) << 4)), g);
    }
#pragma unroll
    for (int i = 0; i < 4; i++) {             // B: 128 rows x 8 chunks of 16B
        int ch = tid + i * 256;
        int r = ch >> 3, c = ch & 7;
        const __nv_bfloat16* g = B + (size_t)(bcol + r) * K + k0 + c * 8;
        cp_async16(smem_u32(sB + r * 128 + ((c ^ (r & 7)) << 4)), g);
    }
}

__global__ __launch_bounds__(256, 1) void bf16_gemm_kernel(
    int M, int N, int K,
    const __nv_bfloat16* __restrict__ A, const __nv_bfloat16* __restrict__ B,
    float* __restrict__ C, const float* __restrict__ bias, int epi)
{
    extern __shared__ char smem_raw[];
    const int tid  = threadIdx.x;
    const int wid  = tid >> 5;
    const int lane = tid & 31;
    const int wm   = (wid >> 1) * 64;    // 0,64,128,192
    const int wn   = (wid & 1) * 64;     // 0,64
    const int brow = blockIdx.y * BM;
    const int bcol = blockIdx.x * BN;

    float acc[4][8][4];
#pragma unroll
    for (int mi = 0; mi < 4; mi++)
#pragma unroll
        for (int ni = 0; ni < 8; ni++)
#pragma unroll
            for (int c = 0; c < 4; c++) acc[mi][ni][c] = 0.f;

    const int KT = K / BKB;

    load_tile_bf(A, B, K, brow, bcol, 0, smem_raw, smem_raw + A_TILE_BYTES, tid);
    cp_commit();
    load_tile_bf(A, B, K, brow, bcol, BKB,
                 smem_raw + STG_BYTES, smem_raw + STG_BYTES + A_TILE_BYTES, tid);
    cp_commit();

    for (int kt = 0; kt < KT; kt++) {
        if (kt + 1 < KT) cp_wait<1>(); else cp_wait<0>();
        __syncthreads();

        if (kt + 2 < KT) {
            int slot = (kt + 2) % NSTAGE;
            load_tile_bf(A, B, K, brow, bcol, (kt + 2) * BKB,
                         smem_raw + slot * STG_BYTES,
                         smem_raw + slot * STG_BYTES + A_TILE_BYTES, tid);
            cp_commit();
        }

        char* sA = smem_raw + (kt % NSTAGE) * STG_BYTES;
        char* sB = sA + A_TILE_BYTES;
        uint32_t aBase = smem_u32(sA);
        uint32_t bBase = smem_u32(sB);

#pragma unroll
        for (int kk = 0; kk < 4; kk++) {
            uint32_t a[4][4], b[4][4];
#pragma unroll
            for (int mi = 0; mi < 4; mi++) {
                int R  = wm + mi * 16 + (lane & 15);
                int Cc = kk * 2 + (lane >> 4);
                LDSM_X4(a[mi], aBase + R * 128 + ((Cc ^ (R & 7)) << 4));
            }
#pragma unroll
            for (int p = 0; p < 4; p++) {
                int R  = wn + p * 16 + (lane & 7) + ((lane >> 4) << 3);
                int Cc = kk * 2 + ((lane >> 3) & 1);
                LDSM_X4(b[p], bBase + R * 128 + ((Cc ^ (R & 7)) << 4));
            }
#pragma unroll
            for (int mi = 0; mi < 4; mi++)
#pragma unroll
                for (int ni = 0; ni < 8; ni++) {
                    uint32_t b0 = b[ni >> 1][(ni & 1) * 2];
                    uint32_t b1 = b[ni >> 1][(ni & 1) * 2 + 1];
                    MMA_BF16(acc[mi][ni], a[mi], b0, b1);
                }
        }
    }

    // ------------------------------ epilogue -------------------------------
    const int erow = lane >> 2;
    const int ecol = (lane & 3) * 2;
#pragma unroll
    for (int mi = 0; mi < 4; mi++) {
#pragma unroll
        for (int ni = 0; ni < 8; ni++) {
            int row = brow + wm + mi * 16 + erow;
            int col = bcol + wn + ni * 8 + ecol;
            if (epi == 0) {
                *(float2*)&C[(size_t)row * N + col] =
                    make_float2(acc[mi][ni][0], acc[mi][ni][1]);
                *(float2*)&C[(size_t)(row + 8) * N + col] =
                    make_float2(acc[mi][ni][2], acc[mi][ni][3]);
            } else {
                float b0 = bias[col], b1 = bias[col + 1];
                float v[4] = {acc[mi][ni][0] + b0, acc[mi][ni][1] + b1,
                              acc[mi][ni][2] + b0, acc[mi][ni][3] + b1};
#pragma unroll
                for (int q = 0; q < 4; q++)
                    v[q] = (v[q] > 20.f) ? v[q] : log1pf(expf(v[q]));
                *(float2*)&C[(size_t)row * N + col] = make_float2(v[0], v[1]);
                *(float2*)&C[(size_t)(row + 8) * N + col] = make_float2(v[2], v[3]);
            }
        }
    }
}

// ============================================================================
// bf16x3 conversion pre-passes
// ============================================================================
// A-side: src (M x K fp32, row stride ld) -> dst (M x 3K bf16): [ah | al | ah]
__global__ __launch_bounds__(256) void convA_bf3(
    const float* __restrict__ src, __nv_bfloat16* __restrict__ dst,
    int ld, int kshift)
{
    int idx = blockIdx.x * 256 + threadIdx.x;
    int K = 1 << kshift;
    int m = idx >> kshift;
    int k = idx & (K - 1);
    float v = src[(size_t)m * ld + k];
    __nv_bfloat16 h = __float2bfloat16(v);
    __nv_bfloat16 l = __float2bfloat16(v - __bfloat162float(h));
    size_t b = (size_t)m * (3 * K);
    dst[b + k] = h;
    dst[b + K + k] = l;
    dst[b + 2 * K + k] = h;
}

// B-side (transpose): src (K x N fp32) -> dst (N x 3K bf16): [bh | bh | bl]
__global__ __launch_bounds__(256) void convB_bf3(
    const float* __restrict__ src, __nv_bfloat16* __restrict__ dst, int K, int N)
{
    __shared__ float t[32][33];
    int k0 = blockIdx.y * 32, n0 = blockIdx.x * 32;
    int tx = threadIdx.x, ty = threadIdx.y;    // (32, 8)
#pragma unroll
    for (int i = 0; i < 4; i++)
        t[ty + 8 * i][tx] = src[(size_t)(k0 + ty + 8 * i) * N + n0 + tx];
    __syncthreads();
#pragma unroll
    for (int i = 0; i < 4; i++) {
        int n = n0 + ty + 8 * i;
        int k = k0 + tx;
        float v = t[tx][ty + 8 * i];
        __nv_bfloat16 h = __float2bfloat16(v);
        __nv_bfloat16 l = __float2bfloat16(v - __bfloat162float(h));
        size_t b = (size_t)n * (3 * K);
        dst[b + k] = h;
        dst[b + K + k] = h;
        dst[b + 2 * K + k] = l;
    }
}

// ============================================================================
// causal depthwise conv1d (K=4) + bias + silu.  8 timesteps per thread.
// ============================================================================
__global__ __launch_bounds__(256) void conv_silu_kernel(
    const float* __restrict__ cw, const float* __restrict__ cb)
{
    int idx = blockIdx.x * 256 + threadIdx.x;   // over (MROWS/8)*DI
    int d    = idx & (DI - 1);
    int rblk = idx >> 11;                        // 8-row block index
    int row0 = rblk * 8;
    int t0   = row0 & (LSEQ - 1);

    float w0 = __ldg(&cw[d * 4 + 0]), w1 = __ldg(&cw[d * 4 + 1]);
    float w2 = __ldg(&cw[d * 4 + 2]), w3 = __ldg(&cw[d * 4 + 3]);
    float bb = cb[d];

    float xv[11];
#pragma unroll
    for (int i = 0; i < 11; i++) {
        int tt = t0 - 3 + i;
        xv[i] = (tt >= 0) ? g_xr[(size_t)(row0 - 3 + i) * (2 * DI) + d] : 0.f;
    }
#pragma unroll
    for (int j = 0; j < 8; j++) {
        float acc = bb + w0 * xv[j] + w1 * xv[j + 1] + w2 * xv[j + 2] + w3 * xv[j + 3];
        g_u[(size_t)(row0 + j) * DI + d] = acc / (1.f + expf(-acc));
    }
}

// ============================================================================
// x_dbl = u @ W_x   (4096 x 2048 x 96)
// ============================================================================
__global__ __launch_bounds__(256) void gemm_xdbl_kernel(const float* __restrict__ Wx)
{
    __shared__ float As[16][64];
    __shared__ float Bs[16][NPROJ];

    const int tid  = threadIdx.x;
    const int brow = blockIdx.x * 64;
    const int ar = tid >> 2;
    const int ak = (tid & 3) * 4;
    const int trow = (tid >> 4) * 4;
    const int tcol = (tid & 15) * 6;

    float acc[4][6];
#pragma unroll
    for (int i = 0; i < 4; i++)
#pragma unroll
        for (int j = 0; j < 6; j++) acc[i][j] = 0.f;

    for (int k0 = 0; k0 < DI; k0 += 16) {
        {
            float4 v = *(const float4*)&g_u[(size_t)(brow + ar) * DI + k0 + ak];
            As[ak + 0][ar] = v.x;
            As[ak + 1][ar] = v.y;
            As[ak + 2][ar] = v.z;
            As[ak + 3][ar] = v.w;
        }
#pragma unroll
        for (int i = 0; i < 6; i++) {
            int idx = tid + i * 256;
            int r = idx / NPROJ;
            int c = idx - r * NPROJ;
            Bs[r][c] = Wx[(size_t)(k0 + r) * NPROJ + c];
        }
        __syncthreads();

#pragma unroll
        for (int k = 0; k < 16; k++) {
            float ra[4], rb[6];
#pragma unroll
            for (int i = 0; i < 4; i++) ra[i] = As[k][trow + i];
#pragma unroll
            for (int j = 0; j < 6; j++) rb[j] = Bs[k][tcol + j];
#pragma unroll
            for (int i = 0; i < 4; i++)
#pragma unroll
                for (int j = 0; j < 6; j++) acc[i][j] += ra[i] * rb[j];
        }
        __syncthreads();
    }

#pragma unroll
    for (int i = 0; i < 4; i++)
#pragma unroll
        for (int j = 0; j < 6; j++)
            g_xdbl[(size_t)(brow + trow + i) * NPROJ + tcol + j] = acc[i][j];
}

// ============================================================================
// selective scan, fused with  y = (scan + u*D) * silu(res).
// Emits y directly as bf16x3 [yh | yl | yh] into g_ybf (out-proj A operand).
// ============================================================================
#define TCHUNK 64
__global__ __launch_bounds__(128) void scan_kernel(
    const float* __restrict__ A_log, const float* __restrict__ Dp)
{
    __shared__ float sB[TCHUNK][NST];
    __shared__ float sC[TCHUNK][NST];
    __shared__ float sDt[TCHUNK][32];
    __shared__ float sU[TCHUNK][32];
    __shared__ float sR[TCHUNK][32];
    __shared__ float sY[TCHUNK][32];

    const int b    = blockIdx.y;
    const int tid  = threadIdx.x;
    const int dloc = tid >> 2;
    const int ng   = tid & 3;
    const int n0   = ng * 4;
    const int d0   = blockIdx.x * 32;
    const int d    = d0 + dloc;

    float a2[4], h[4];
#pragma unroll
    for (int i = 0; i < 4; i++) {
        a2[i] = -expf(A_log[(size_t)d * NST + n0 + i]) * 1.44269504f;
        h[i] = 0.f;
    }
    const float Dv = Dp[d];

    for (int t0 = 0; t0 < LSEQ; t0 += TCHUNK) {
        for (int idx = tid; idx < TCHUNK * NST; idx += 128) {
            int tt = idx >> 4, n = idx & 15;
            size_t grow = (size_t)(b * LSEQ + t0 + tt) * NPROJ;
            sB[tt][n] = g_xdbl[grow + DTR + n];
            sC[tt][n] = g_xdbl[grow + DTR + NST + n];
        }
        for (int idx = tid; idx < TCHUNK * 32; idx += 128) {
            int tt = idx >> 5, dd = idx & 31;
            size_t base = (size_t)(b * LSEQ + t0 + tt) * DI + d0 + dd;
            sDt[tt][dd] = g_delta[base];
            sU[tt][dd]  = g_u[base];
            sR[tt][dd]  = g_xr[(size_t)(b * LSEQ + t0 + tt) * (2 * DI) + DI + d0 + dd];
        }
        __syncthreads();

        for (int tt = 0; tt < TCHUNK; tt++) {
            float dt_v = sDt[tt][dloc];
            float u_v  = sU[tt][dloc];
            float du   = dt_v * u_v;
            float yp = 0.f;
#pragma unroll
            for (int i = 0; i < 4; i++) {
                h[i] = fast_ex2(dt_v * a2[i]) * h[i] + du * sB[tt][n0 + i];
                yp += h[i] * sC[tt][n0 + i];
            }
            yp += __shfl_xor_sync(0xffffffffu, yp, 1);
            yp += __shfl_xor_sync(0xffffffffu, yp, 2);
            if (ng == 0) {
                float res = sR[tt][dloc];
                float sil = res / (1.f + expf(-res));
                sY[tt][dloc] = (yp + u_v * Dv) * sil;
            }
        }
        __syncthreads();

        // cooperative coalesced bf16x3 writeout of this chunk
        for (int idx = tid; idx < TCHUNK * 32; idx += 128) {
            int tt = idx >> 5, dd = idx & 31;
            float v = sY[tt][dd];
            __nv_bfloat16 hh = __float2bfloat16(v);
            __nv_bfloat16 ll = __float2bfloat16(v - __bfloat162float(hh));
            size_t base = (size_t)(b * LSEQ + t0 + tt) * (3 * DI) + d0 + dd;
            g_ybf[base]          = hh;
            g_ybf[base + DI]     = ll;
            g_ybf[base + 2 * DI] = hh;
        }
        __syncthreads();
    }
}

// ============================================================================
// host launch
// ============================================================================
extern "C" void kernel_launch(void* const* d_in, const int* in_sizes, int n_in,
                              void* d_out, int out_size)
{
    const float* x      = (const float*)d_in[0];
    const float* W_in   = (const float*)d_in[1];
    const float* conv_w = (const float*)d_in[2];
    const float* conv_b = (const float*)d_in[3];
    const float* W_x    = (const float*)d_in[4];
    const float* W_dt   = (const float*)d_in[5];
    const float* b_dt   = (const float*)d_in[6];
    const float* A_log  = (const float*)d_in[7];
    const float* Dp     = (const float*)d_in[8];
    const float* W_out  = (const float*)d_in[9];
    float* out          = (float*)d_out;

    float *p_xr, *p_xdbl, *p_delta;
    cudaGetSymbolAddress((void**)&p_xr,    g_xr);
    cudaGetSymbolAddress((void**)&p_xdbl,  g_xdbl);
    cudaGetSymbolAddress((void**)&p_delta, g_delta);

    __nv_bfloat16 *p_xbf, *p_wibf, *p_ybf, *p_wobf, *p_xdblbf, *p_wdtbf;
    cudaGetSymbolAddress((void**)&p_xbf,    g_xbf);
    cudaGetSymbolAddress((void**)&p_wibf,   g_wibf);
    cudaGetSymbolAddress((void**)&p_ybf,    g_ybf);
    cudaGetSymbolAddress((void**)&p_wobf,   g_wobf);
    cudaGetSymbolAddress((void**)&p_xdblbf, g_xdblbf);
    cudaGetSymbolAddress((void**)&p_wdtbf,  g_wdtbf);

    cudaFuncSetAttribute(bf16_gemm_kernel,
                         cudaFuncAttributeMaxDynamicSharedMemorySize, GEMM_SMEM);

    // 0. expand x and W_in^T to bf16x3
    convA_bf3<<<(MROWS * DM) / 256, 256>>>(x, p_xbf, DM, 10);
    convB_bf3<<<dim3((2 * DI) / 32, DM / 32), dim3(32, 8)>>>(W_in, p_wibf, DM, 2 * DI);

    // 1. in-projection: (4096 x 3072) @ (3072 x 4096)
    bf16_gemm_kernel<<<dim3((2 * DI) / BN, MROWS / BM), 256, GEMM_SMEM>>>(
        MROWS, 2 * DI, 3 * DM, p_xbf, p_wibf, p_xr, nullptr, 0);

    // 2. causal depthwise conv + silu (8 timesteps per thread)
    conv_silu_kernel<<<(MROWS / 8) * DI / 256, 256>>>(conv_w, conv_b);

    // 3. x_dbl = u @ W_x
    gemm_xdbl_kernel<<<MROWS / 64, 256>>>(W_x);

    // 4. delta = softplus(x_dbl[:, :64] @ W_dt + b_dt)  (bf16x3, fused epi)
    convA_bf3<<<(MROWS * DTR) / 256, 256>>>(p_xdbl, p_xdblbf, NPROJ, 6);
    convB_bf3<<<dim3(DI / 32, DTR / 32), dim3(32, 8)>>>(W_dt, p_wdtbf, DTR, DI);
    bf16_gemm_kernel<<<dim3(DI / BN, MROWS / BM), 256, GEMM_SMEM>>>(
        MROWS, DI, 3 * DTR, p_xdblbf, p_wdtbf, p_delta, b_dt, 1);

    // 5. selective scan + gating epilogue, emits bf16x3 y directly
    scan_kernel<<<dim3(DI / 32, BATCH), 128>>>(A_log, Dp);

    // 5b. expand W_out^T to bf16x3
    convB_bf3<<<dim3(DM / 32, DI / 32), dim3(32, 8)>>>(W_out, p_wobf, DI, DM);

    // 6. out-projection: (4096 x 6144) @ (6144 x 1024)
    bf16_gemm_kernel<<<dim3(DM / BN, MROWS / BM), 256, GEMM_SMEM>>>(
        MROWS, DM, 3 * DI, p_ybf, p_wobf, out, nullptr, 0);
}

// round 8
// speedup vs baseline: 1.0474x; 1.0474x over previous
#include <cuda_runtime.h>
#include <cuda_bf16.h>
#include <stdint.h>
#include <math.h>

// ---------------------------------------------------------------------------
// Mamba block forward.  B=2, L=2048, d_model=1024, d_inner=2048,
// d_state=16, dt_rank=64, d_conv=4
// ---------------------------------------------------------------------------
#define LSEQ   2048
#define BATCH  2
#define DM     1024
#define DI     2048
#define NST    16
#define DTR    64
#define MROWS  (BATCH * LSEQ)   // 4096
#define NPROJ  96               // dt_rank + 2*d_state

// ------------------------- scratch (static device mem) ---------------------
__device__ float g_xr[(size_t)MROWS * (2 * DI)];   // in-proj output (xin|res)
__device__ float g_u[(size_t)MROWS * DI];          // silu(conv(xin))
__device__ float g_xdbl[(size_t)MROWS * NPROJ];    // u @ W_x
__device__ float g_delta[(size_t)MROWS * DI];      // softplus(dlt@W_dt + b)

// bf16x3 expanded operands: A' = [ah|al|ah] (M x 3K),  B'^T = [bh|bh|bl] (N x 3K)
__device__ __align__(1024) __nv_bfloat16 g_xbf  [(size_t)MROWS * (3 * DM)];
__device__ __align__(1024) __nv_bfloat16 g_wibf [(size_t)(2 * DI) * (3 * DM)];
__device__ __align__(1024) __nv_bfloat16 g_ybf  [(size_t)MROWS * (3 * DI)];   // written by scan
__device__ __align__(1024) __nv_bfloat16 g_wobf [(size_t)DM * (3 * DI)];
__device__ __align__(1024) __nv_bfloat16 g_xdblbf[(size_t)MROWS * (3 * DTR)];
__device__ __align__(1024) __nv_bfloat16 g_wdtbf [(size_t)DI * (3 * DTR)];

// ------------------------- helpers ------------------------------------------
__device__ __forceinline__ float fast_ex2(float x) {
    float y;
    asm("ex2.approx.f32 %0, %1;" : "=f"(y) : "f"(x));
    return y;
}
__device__ __forceinline__ uint32_t smem_u32(const void* p) {
    uint32_t a;
    asm("{ .reg .u64 t; cvta.to.shared.u64 t, %1; cvt.u32.u64 %0, t; }" : "=r"(a) : "l"(p));
    return a;
}
__device__ __forceinline__ void cp_async16(uint32_t saddr, const void* gptr) {
    asm volatile("cp.async.cg.shared.global [%0], [%1], 16;\n" :: "r"(saddr), "l"(gptr));
}
__device__ __forceinline__ void cp_commit() {
    asm volatile("cp.async.commit_group;\n");
}
template <int NWAIT> __device__ __forceinline__ void cp_wait() {
    asm volatile("cp.async.wait_group %0;\n" :: "n"(NWAIT));
}

#define LDSM_X4(r, addr)                                                       \
    asm volatile("ldmatrix.sync.aligned.m8n8.x4.shared.b16 {%0,%1,%2,%3}, [%4];" \
                 : "=r"((r)[0]), "=r"((r)[1]), "=r"((r)[2]), "=r"((r)[3])      \
                 : "r"(addr))

#define MMA_BF16(ACC, Aq, B0, B1)                                              \
    asm volatile(                                                              \
        "mma.sync.aligned.m16n8k16.row.col.f32.bf16.bf16.f32 "                 \
        "{%0,%1,%2,%3}, {%4,%5,%6,%7}, {%8,%9}, {%0,%1,%2,%3};\n"              \
        : "+f"(ACC[0]), "+f"(ACC[1]), "+f"(ACC[2]), "+f"(ACC[3])               \
        : "r"((Aq)[0]), "r"((Aq)[1]), "r"((Aq)[2]), "r"((Aq)[3]),              \
          "r"(B0), "r"(B1))

// ============================================================================
// bf16 tensor-core GEMM:  C(MxN fp32) = A(M x K) @ B(N x K)^T,  bf16 inputs.
// CTA 128x128, BK=64, 8 warps (2x4), warp tile 64x32, m16n8k16.
// 3-stage cp.async pipeline, XOR-swizzled smem, ldmatrix fragment loads,
// b-fragment double-buffer.  epi: 0 = plain store, 1 = softplus(acc + bias).
// ============================================================================
#define BM 128
#define BN 128
#define BKB 64
#define TILE_BYTES (BM * BKB * 2)    // 16384 per operand
#define STG_BYTES  (2 * TILE_BYTES)  // 32768 per stage
#define NSTAGE 3
#define GEMM_SMEM (NSTAGE * STG_BYTES)   // 98304  (2 CTAs / SM)

__device__ __forceinline__ void load_tile_bf(
    const __nv_bfloat16* __restrict__ A, const __nv_bfloat16* __restrict__ B,
    int K, int brow, int bcol, int k0, char* sA, char* sB, int tid)
{
#pragma unroll
    for (int i = 0; i < 4; i++) {             // A: 128 rows x 8 chunks of 16B
        int ch = tid + i * 256;
        int r = ch >> 3, c = ch & 7;
        const __nv_bfloat16* g = A + (size_t)(brow + r) * K + k0 + c * 8;
        cp_async16(smem_u32(sA + r * 128 + ((c ^ (r & 7)) << 4)), g);
    }
#pragma unroll
    for (int i = 0; i < 4; i++) {             // B: 128 rows x 8 chunks of 16B
        int ch = tid + i * 256;
        int r = ch >> 3, c = ch & 7;
        const __nv_bfloat16* g = B + (size_t)(bcol + r) * K + k0 + c * 8;
        cp_async16(smem_u32(sB + r * 128 + ((c ^ (r & 7)) << 4)), g);
    }
}

__global__ __launch_bounds__(256, 2) void bf16_gemm_kernel(
    int M, int N, int K,
    const __nv_bfloat16* __restrict__ A, const __nv_bfloat16* __restrict__ B,
    float* __restrict__ C, const float* __restrict__ bias, int epi)
{
    extern __shared__ char smem_raw[];
    const int tid  = threadIdx.x;
    const int wid  = tid >> 5;
    const int lane = tid & 31;
    const int wm   = (wid >> 2) * 64;
    const int wn   = (wid & 3) * 32;
    const int brow = blockIdx.y * BM;
    const int bcol = blockIdx.x * BN;

    float acc[4][4][4];
#pragma unroll
    for (int mi = 0; mi < 4; mi++)
#pragma unroll
        for (int ni = 0; ni < 4; ni++)
#pragma unroll
            for (int c = 0; c < 4; c++) acc[mi][ni][c] = 0.f;

    const int KT = K / BKB;

    load_tile_bf(A, B, K, brow, bcol, 0, smem_raw, smem_raw + TILE_BYTES, tid);
    cp_commit();
    load_tile_bf(A, B, K, brow, bcol, BKB,
                 smem_raw + STG_BYTES, smem_raw + STG_BYTES + TILE_BYTES, tid);
    cp_commit();

    // b-fragment LDSM address helper indices (R-within-warp-tile constant)
    const int bR   = (lane & 7) + ((lane >> 4) << 3);       // 0..15
    const int bCsel = (lane >> 3) & 1;

    for (int kt = 0; kt < KT; kt++) {
        if (kt + 1 < KT) cp_wait<1>(); else cp_wait<0>();
        __syncthreads();

        if (kt + 2 < KT) {
            int slot = (kt + 2) % NSTAGE;
            load_tile_bf(A, B, K, brow, bcol, (kt + 2) * BKB,
                         smem_raw + slot * STG_BYTES,
                         smem_raw + slot * STG_BYTES + TILE_BYTES, tid);
            cp_commit();
        }

        char* sA = smem_raw + (kt % NSTAGE) * STG_BYTES;
        char* sB = sA + TILE_BYTES;
        uint32_t aBase = smem_u32(sA);
        uint32_t bBase = smem_u32(sB);

        uint32_t bbuf[2][2][4];
        // preload b-frags for kk = 0
#pragma unroll
        for (int p = 0; p < 2; p++) {
            int R  = wn + p * 16 + bR;
            int Cc = bCsel;
            LDSM_X4(bbuf[0][p], bBase + R * 128 + ((Cc ^ (R & 7)) << 4));
        }

#pragma unroll
        for (int kk = 0; kk < 4; kk++) {
            uint32_t a[4][4];
#pragma unroll
            for (int mi = 0; mi < 4; mi++) {
                int R  = wm + mi * 16 + (lane & 15);
                int Cc = kk * 2 + (lane >> 4);
                LDSM_X4(a[mi], aBase + R * 128 + ((Cc ^ (R & 7)) << 4));
            }
            if (kk < 3) {
#pragma unroll
                for (int p = 0; p < 2; p++) {
                    int R  = wn + p * 16 + bR;
                    int Cc = (kk + 1) * 2 + bCsel;
                    LDSM_X4(bbuf[(kk + 1) & 1][p], bBase + R * 128 + ((Cc ^ (R & 7)) << 4));
                }
            }
            uint32_t (*b)[4] = bbuf[kk & 1];
#pragma unroll
            for (int mi = 0; mi < 4; mi++)
#pragma unroll
                for (int ni = 0; ni < 4; ni++) {
                    uint32_t b0 = b[ni >> 1][(ni & 1) * 2];
                    uint32_t b1 = b[ni >> 1][(ni & 1) * 2 + 1];
                    MMA_BF16(acc[mi][ni], a[mi], b0, b1);
                }
        }
    }

    // ------------------------------ epilogue -------------------------------
    const int erow = lane >> 2;
    const int ecol = (lane & 3) * 2;
#pragma unroll
    for (int mi = 0; mi < 4; mi++) {
#pragma unroll
        for (int ni = 0; ni < 4; ni++) {
            int row = brow + wm + mi * 16 + erow;
            int col = bcol + wn + ni * 8 + ecol;
            if (epi == 0) {
                *(float2*)&C[(size_t)row * N + col] =
                    make_float2(acc[mi][ni][0], acc[mi][ni][1]);
                *(float2*)&C[(size_t)(row + 8) * N + col] =
                    make_float2(acc[mi][ni][2], acc[mi][ni][3]);
            } else {
                float b0 = bias[col], b1 = bias[col + 1];
                float v[4] = {acc[mi][ni][0] + b0, acc[mi][ni][1] + b1,
                              acc[mi][ni][2] + b0, acc[mi][ni][3] + b1};
#pragma unroll
                for (int q = 0; q < 4; q++)
                    v[q] = (v[q] > 20.f) ? v[q] : log1pf(expf(v[q]));
                *(float2*)&C[(size_t)row * N + col] = make_float2(v[0], v[1]);
                *(float2*)&C[(size_t)(row + 8) * N + col] = make_float2(v[2], v[3]);
            }
        }
    }
}

// ============================================================================
// bf16x3 conversion pre-passes
// ============================================================================
// A-side: src (M x K fp32, row stride ld) -> dst (M x 3K bf16): [ah | al | ah]
__global__ __launch_bounds__(256) void convA_bf3(
    const float* __restrict__ src, __nv_bfloat16* __restrict__ dst,
    int ld, int kshift)
{
    int idx = blockIdx.x * 256 + threadIdx.x;
    int K = 1 << kshift;
    int m = idx >> kshift;
    int k = idx & (K - 1);
    float v = src[(size_t)m * ld + k];
    __nv_bfloat16 h = __float2bfloat16(v);
    __nv_bfloat16 l = __float2bfloat16(v - __bfloat162float(h));
    size_t b = (size_t)m * (3 * K);
    dst[b + k] = h;
    dst[b + K + k] = l;
    dst[b + 2 * K + k] = h;
}

// B-side (transpose): src (K x N fp32) -> dst (N x 3K bf16): [bh | bh | bl]
__global__ __launch_bounds__(256) void convB_bf3(
    const float* __restrict__ src, __nv_bfloat16* __restrict__ dst, int K, int N)
{
    __shared__ float t[32][33];
    int k0 = blockIdx.y * 32, n0 = blockIdx.x * 32;
    int tx = threadIdx.x, ty = threadIdx.y;    // (32, 8)
#pragma unroll
    for (int i = 0; i < 4; i++)
        t[ty + 8 * i][tx] = src[(size_t)(k0 + ty + 8 * i) * N + n0 + tx];
    __syncthreads();
#pragma unroll
    for (int i = 0; i < 4; i++) {
        int n = n0 + ty + 8 * i;
        int k = k0 + tx;
        float v = t[tx][ty + 8 * i];
        __nv_bfloat16 h = __float2bfloat16(v);
        __nv_bfloat16 l = __float2bfloat16(v - __bfloat162float(h));
        size_t b = (size_t)n * (3 * K);
        dst[b + k] = h;
        dst[b + K + k] = h;
        dst[b + 2 * K + k] = l;
    }
}

// ============================================================================
// causal depthwise conv1d (K=4) + bias + silu.  8 timesteps per thread.
// ============================================================================
__global__ __launch_bounds__(256) void conv_silu_kernel(
    const float* __restrict__ cw, const float* __restrict__ cb)
{
    int idx = blockIdx.x * 256 + threadIdx.x;   // over (MROWS/8)*DI
    int d    = idx & (DI - 1);
    int rblk = idx >> 11;                        // 8-row block index
    int row0 = rblk * 8;
    int t0   = row0 & (LSEQ - 1);

    float w0 = __ldg(&cw[d * 4 + 0]), w1 = __ldg(&cw[d * 4 + 1]);
    float w2 = __ldg(&cw[d * 4 + 2]), w3 = __ldg(&cw[d * 4 + 3]);
    float bb = cb[d];

    float xv[11];
#pragma unroll
    for (int i = 0; i < 11; i++) {
        int tt = t0 - 3 + i;
        xv[i] = (tt >= 0) ? g_xr[(size_t)(row0 - 3 + i) * (2 * DI) + d] : 0.f;
    }
#pragma unroll
    for (int j = 0; j < 8; j++) {
        float acc = bb + w0 * xv[j] + w1 * xv[j + 1] + w2 * xv[j + 2] + w3 * xv[j + 3];
        g_u[(size_t)(row0 + j) * DI + d] = acc / (1.f + expf(-acc));
    }
}

// ============================================================================
// x_dbl = u @ W_x   (4096 x 2048 x 96)
// ============================================================================
__global__ __launch_bounds__(256) void gemm_xdbl_kernel(const float* __restrict__ Wx)
{
    __shared__ float As[16][64];
    __shared__ float Bs[16][NPROJ];

    const int tid  = threadIdx.x;
    const int brow = blockIdx.x * 64;
    const int ar = tid >> 2;
    const int ak = (tid & 3) * 4;
    const int trow = (tid >> 4) * 4;
    const int tcol = (tid & 15) * 6;

    float acc[4][6];
#pragma unroll
    for (int i = 0; i < 4; i++)
#pragma unroll
        for (int j = 0; j < 6; j++) acc[i][j] = 0.f;

    for (int k0 = 0; k0 < DI; k0 += 16) {
        {
            float4 v = *(const float4*)&g_u[(size_t)(brow + ar) * DI + k0 + ak];
            As[ak + 0][ar] = v.x;
            As[ak + 1][ar] = v.y;
            As[ak + 2][ar] = v.z;
            As[ak + 3][ar] = v.w;
        }
#pragma unroll
        for (int i = 0; i < 6; i++) {
            int idx = tid + i * 256;
            int r = idx / NPROJ;
            int c = idx - r * NPROJ;
            Bs[r][c] = Wx[(size_t)(k0 + r) * NPROJ + c];
        }
        __syncthreads();

#pragma unroll
        for (int k = 0; k < 16; k++) {
            float ra[4], rb[6];
#pragma unroll
            for (int i = 0; i < 4; i++) ra[i] = As[k][trow + i];
#pragma unroll
            for (int j = 0; j < 6; j++) rb[j] = Bs[k][tcol + j];
#pragma unroll
            for (int i = 0; i < 4; i++)
#pragma unroll
                for (int j = 0; j < 6; j++) acc[i][j] += ra[i] * rb[j];
        }
        __syncthreads();
    }

#pragma unroll
    for (int i = 0; i < 4; i++)
#pragma unroll
        for (int j = 0; j < 6; j++)
            g_xdbl[(size_t)(brow + trow + i) * NPROJ + tcol + j] = acc[i][j];
}

// ============================================================================
// selective scan, fused with  y = (scan + u*D) * silu(res).
// Emits y directly as bf16x3 [yh | yl | yh] into g_ybf (out-proj A operand).
// ============================================================================
#define TCHUNK 64
__global__ __launch_bounds__(128) void scan_kernel(
    const float* __restrict__ A_log, const float* __restrict__ Dp)
{
    __shared__ float sB[TCHUNK][NST];
    __shared__ float sC[TCHUNK][NST];
    __shared__ float sDt[TCHUNK][32];
    __shared__ float sU[TCHUNK][32];
    __shared__ float sR[TCHUNK][32];
    __shared__ float sY[TCHUNK][32];

    const int b    = blockIdx.y;
    const int tid  = threadIdx.x;
    const int dloc = tid >> 2;
    const int ng   = tid & 3;
    const int n0   = ng * 4;
    const int d0   = blockIdx.x * 32;
    const int d    = d0 + dloc;

    float a2[4], h[4];
#pragma unroll
    for (int i = 0; i < 4; i++) {
        a2[i] = -expf(A_log[(size_t)d * NST + n0 + i]) * 1.44269504f;
        h[i] = 0.f;
    }
    const float Dv = Dp[d];

    for (int t0 = 0; t0 < LSEQ; t0 += TCHUNK) {
        for (int idx = tid; idx < TCHUNK * NST; idx += 128) {
            int tt = idx >> 4, n = idx & 15;
            size_t grow = (size_t)(b * LSEQ + t0 + tt) * NPROJ;
            sB[tt][n] = g_xdbl[grow + DTR + n];
            sC[tt][n] = g_xdbl[grow + DTR + NST + n];
        }
        for (int idx = tid; idx < TCHUNK * 32; idx += 128) {
            int tt = idx >> 5, dd = idx & 31;
            size_t base = (size_t)(b * LSEQ + t0 + tt) * DI + d0 + dd;
            sDt[tt][dd] = g_delta[base];
            sU[tt][dd]  = g_u[base];
            sR[tt][dd]  = g_xr[(size_t)(b * LSEQ + t0 + tt) * (2 * DI) + DI + d0 + dd];
        }
        __syncthreads();

        for (int tt = 0; tt < TCHUNK; tt++) {
            float dt_v = sDt[tt][dloc];
            float u_v  = sU[tt][dloc];
            float du   = dt_v * u_v;
            float yp = 0.f;
#pragma unroll
            for (int i = 0; i < 4; i++) {
                h[i] = fast_ex2(dt_v * a2[i]) * h[i] + du * sB[tt][n0 + i];
                yp += h[i] * sC[tt][n0 + i];
            }
            yp += __shfl_xor_sync(0xffffffffu, yp, 1);
            yp += __shfl_xor_sync(0xffffffffu, yp, 2);
            if (ng == 0) {
                float res = sR[tt][dloc];
                float sil = res / (1.f + expf(-res));
                sY[tt][dloc] = (yp + u_v * Dv) * sil;
            }
        }
        __syncthreads();

        // cooperative coalesced bf16x3 writeout of this chunk
        for (int idx = tid; idx < TCHUNK * 32; idx += 128) {
            int tt = idx >> 5, dd = idx & 31;
            float v = sY[tt][dd];
            __nv_bfloat16 hh = __float2bfloat16(v);
            __nv_bfloat16 ll = __float2bfloat16(v - __bfloat162float(hh));
            size_t base = (size_t)(b * LSEQ + t0 + tt) * (3 * DI) + d0 + dd;
            g_ybf[base]          = hh;
            g_ybf[base + DI]     = ll;
            g_ybf[base + 2 * DI] = hh;
        }
        __syncthreads();
    }
}

// ============================================================================
// host launch
// ============================================================================
extern "C" void kernel_launch(void* const* d_in, const int* in_sizes, int n_in,
                              void* d_out, int out_size)
{
    const float* x      = (const float*)d_in[0];
    const float* W_in   = (const float*)d_in[1];
    const float* conv_w = (const float*)d_in[2];
    const float* conv_b = (const float*)d_in[3];
    const float* W_x    = (const float*)d_in[4];
    const float* W_dt   = (const float*)d_in[5];
    const float* b_dt   = (const float*)d_in[6];
    const float* A_log  = (const float*)d_in[7];
    const float* Dp     = (const float*)d_in[8];
    const float* W_out  = (const float*)d_in[9];
    float* out          = (float*)d_out;

    float *p_xr, *p_xdbl, *p_delta;
    cudaGetSymbolAddress((void**)&p_xr,    g_xr);
    cudaGetSymbolAddress((void**)&p_xdbl,  g_xdbl);
    cudaGetSymbolAddress((void**)&p_delta, g_delta);

    __nv_bfloat16 *p_xbf, *p_wibf, *p_ybf, *p_wobf, *p_xdblbf, *p_wdtbf;
    cudaGetSymbolAddress((void**)&p_xbf,    g_xbf);
    cudaGetSymbolAddress((void**)&p_wibf,   g_wibf);
    cudaGetSymbolAddress((void**)&p_ybf,    g_ybf);
    cudaGetSymbolAddress((void**)&p_wobf,   g_wobf);
    cudaGetSymbolAddress((void**)&p_xdblbf, g_xdblbf);
    cudaGetSymbolAddress((void**)&p_wdtbf,  g_wdtbf);

    cudaFuncSetAttribute(bf16_gemm_kernel,
                         cudaFuncAttributeMaxDynamicSharedMemorySize, GEMM_SMEM);

    // 0. expand x and W_in^T to bf16x3
    convA_bf3<<<(MROWS * DM) / 256, 256>>>(x, p_xbf, DM, 10);
    convB_bf3<<<dim3((2 * DI) / 32, DM / 32), dim3(32, 8)>>>(W_in, p_wibf, DM, 2 * DI);

    // 1. in-projection: (4096 x 3072) @ (3072 x 4096)
    bf16_gemm_kernel<<<dim3((2 * DI) / BN, MROWS / BM), 256, GEMM_SMEM>>>(
        MROWS, 2 * DI, 3 * DM, p_xbf, p_wibf, p_xr, nullptr, 0);

    // 2. causal depthwise conv + silu (8 timesteps per thread)
    conv_silu_kernel<<<(MROWS / 8) * DI / 256, 256>>>(conv_w, conv_b);

    // 3. x_dbl = u @ W_x
    gemm_xdbl_kernel<<<MROWS / 64, 256>>>(W_x);

    // 4. delta = softplus(x_dbl[:, :64] @ W_dt + b_dt)  (bf16x3, fused epi)
    convA_bf3<<<(MROWS * DTR) / 256, 256>>>(p_xdbl, p_xdblbf, NPROJ, 6);
    convB_bf3<<<dim3(DI / 32, DTR / 32), dim3(32, 8)>>>(W_dt, p_wdtbf, DTR, DI);
    bf16_gemm_kernel<<<dim3(DI / BN, MROWS / BM), 256, GEMM_SMEM>>>(
        MROWS, DI, 3 * DTR, p_xdblbf, p_wdtbf, p_delta, b_dt, 1);

    // 5. selective scan + gating epilogue, emits bf16x3 y directly
    scan_kernel<<<dim3(DI / 32, BATCH), 128>>>(A_log, Dp);

    // 5b. expand W_out^T to bf16x3
    convB_bf3<<<dim3(DM / 32, DI / 32), dim3(32, 8)>>>(W_out, p_wobf, DI, DM);

    // 6. out-projection: (4096 x 6144) @ (6144 x 1024)
    bf16_gemm_kernel<<<dim3(DM / BN, MROWS / BM), 256, GEMM_SMEM>>>(
        MROWS, DM, 3 * DI, p_ybf, p_wobf, out, nullptr, 0);
}